// round 1
// baseline (speedup 1.0000x reference)
#include <cuda_runtime.h>
#include <cuda_bf16.h>
#include <math.h>

// ---------------------------------------------------------------------------
// BertBiAttention: two-stream cross attention
//   B=16, S1=256 (vision), S2=512 (text), V_HID=1024, T_HID=768,
//   BI_HID=1024, H=8, D=128
// Pipeline:
//   1) 6x SGEMM+bias  -> q1,k1,v1 (4096x1024), q2,k2,v2 (8192x1024)
//   2) scores1 = q2@k1^T*scale + mask1 ; softmax ; context1 = p1@v1 -> out[0:...]
//   3) scores2 = q1@k2^T*scale + mask2 ; softmax ; context2 = p2@v2 -> out[C1:]
// All fp32 SIMT (baseline round; tensor-core port comes next).
// ---------------------------------------------------------------------------

#define BB   16
#define SS1  256
#define SS2  512
#define HH   8
#define DD   128
#define HD   1024          // HH*DD
#define C1_ELEMS ((size_t)BB * SS2 * HD)   // context1 size = 8388608
#define C2_ELEMS ((size_t)BB * SS1 * HD)   // context2 size = 4194304

// Scratch (device globals: no allocation allowed)
__device__ float g_q1[BB * SS1 * HD];
__device__ float g_k1[BB * SS1 * HD];
__device__ float g_v1[BB * SS1 * HD];
__device__ float g_q2[BB * SS2 * HD];
__device__ float g_k2[BB * SS2 * HD];
__device__ float g_v2[BB * SS2 * HD];
__device__ float g_p1[(size_t)BB * HH * SS2 * SS1];  // probs1 [bh][S2][S1]
__device__ float g_p2[(size_t)BB * HH * SS1 * SS2];  // probs2 [bh][S1][S2]

// ---------------------------------------------------------------------------
// SGEMM + bias: C[M,N] = A[M,K] @ W[K,N] + bias[N]
// BM=BN=128, BK=16, 256 threads, 8x8 microtile split 4+4 (conflict-free LDS.128)
// Requires M%128==0, N%128==0, K%16==0 (true for all 6 calls).
// ---------------------------------------------------------------------------
__global__ __launch_bounds__(256, 2) void sgemm_bias(
    const float* __restrict__ A, const float* __restrict__ W,
    const float* __restrict__ bias, float* __restrict__ C,
    int M, int N, int K)
{
    __shared__ float As[16][128 + 4];
    __shared__ float Ws[16][128 + 4];
    const int tid = threadIdx.x;
    const int tx  = tid & 15;
    const int ty  = tid >> 4;
    const int bm  = blockIdx.y * 128;
    const int bn  = blockIdx.x * 128;

    float acc[8][8];
#pragma unroll
    for (int i = 0; i < 8; i++)
#pragma unroll
        for (int j = 0; j < 8; j++) acc[i][j] = 0.f;

    const int av = tid * 2;
    for (int k0 = 0; k0 < K; k0 += 16) {
#pragma unroll
        for (int u = 0; u < 2; u++) {
            int v   = av + u;
            int row = v >> 2;
            int kq  = (v & 3) << 2;
            float4 a4 = *reinterpret_cast<const float4*>(
                A + (size_t)(bm + row) * K + k0 + kq);
            As[kq + 0][row] = a4.x; As[kq + 1][row] = a4.y;
            As[kq + 2][row] = a4.z; As[kq + 3][row] = a4.w;
            int wr = v >> 5;
            int nq = (v & 31) << 2;
            float4 w4 = *reinterpret_cast<const float4*>(
                W + (size_t)(k0 + wr) * N + bn + nq);
            *reinterpret_cast<float4*>(&Ws[wr][nq]) = w4;
        }
        __syncthreads();
#pragma unroll
        for (int kk = 0; kk < 16; kk++) {
            float a[8], b[8];
            float4 t;
            t = *reinterpret_cast<const float4*>(&As[kk][ty * 4]);
            a[0] = t.x; a[1] = t.y; a[2] = t.z; a[3] = t.w;
            t = *reinterpret_cast<const float4*>(&As[kk][64 + ty * 4]);
            a[4] = t.x; a[5] = t.y; a[6] = t.z; a[7] = t.w;
            t = *reinterpret_cast<const float4*>(&Ws[kk][tx * 4]);
            b[0] = t.x; b[1] = t.y; b[2] = t.z; b[3] = t.w;
            t = *reinterpret_cast<const float4*>(&Ws[kk][64 + tx * 4]);
            b[4] = t.x; b[5] = t.y; b[6] = t.z; b[7] = t.w;
#pragma unroll
            for (int i = 0; i < 8; i++)
#pragma unroll
                for (int j = 0; j < 8; j++)
                    acc[i][j] = fmaf(a[i], b[j], acc[i][j]);
        }
        __syncthreads();
    }

#pragma unroll
    for (int i = 0; i < 8; i++) {
        int m = bm + ((i < 4) ? (ty * 4 + i) : (64 + ty * 4 + i - 4));
#pragma unroll
        for (int jj = 0; jj < 2; jj++) {
            int n = bn + ((jj == 0) ? (tx * 4) : (64 + tx * 4));
            float4 o;
            o.x = acc[i][jj * 4 + 0] + bias[n + 0];
            o.y = acc[i][jj * 4 + 1] + bias[n + 1];
            o.z = acc[i][jj * 4 + 2] + bias[n + 2];
            o.w = acc[i][jj * 4 + 3] + bias[n + 3];
            *reinterpret_cast<float4*>(C + (size_t)m * N + n) = o;
        }
    }
}

// ---------------------------------------------------------------------------
// scores[bh][m][n] = scale * sum_d Q[b,m,h,d]*Km[b,n,h,d] + mask[b,n]
// grid: (Sk/64, Sq/64, B*H), 256 threads, 64x64 tile, 4x4 microtile, BK=16 (d)
// ---------------------------------------------------------------------------
__global__ __launch_bounds__(256) void attn_scores(
    const float* __restrict__ Q, const float* __restrict__ Km,
    const float* __restrict__ mask, float* __restrict__ S,
    int Sq, int Sk, float scale)
{
    __shared__ float Qs[16][64 + 4];
    __shared__ float Ks[16][64 + 4];
    const int tid = threadIdx.x, tx = tid & 15, ty = tid >> 4;
    const int bh = blockIdx.z, b = bh >> 3, h = bh & 7;
    const int m0 = blockIdx.y * 64, n0 = blockIdx.x * 64;

    float acc[4][4];
#pragma unroll
    for (int i = 0; i < 4; i++)
#pragma unroll
        for (int j = 0; j < 4; j++) acc[i][j] = 0.f;

    for (int d0 = 0; d0 < DD; d0 += 16) {
        {
            int v = tid;
            int row = v >> 2, dq = (v & 3) << 2;
            float4 q4 = *reinterpret_cast<const float4*>(
                Q + ((size_t)(b * Sq + m0 + row) * HH + h) * DD + d0 + dq);
            Qs[dq + 0][row] = q4.x; Qs[dq + 1][row] = q4.y;
            Qs[dq + 2][row] = q4.z; Qs[dq + 3][row] = q4.w;
            float4 k4 = *reinterpret_cast<const float4*>(
                Km + ((size_t)(b * Sk + n0 + row) * HH + h) * DD + d0 + dq);
            Ks[dq + 0][row] = k4.x; Ks[dq + 1][row] = k4.y;
            Ks[dq + 2][row] = k4.z; Ks[dq + 3][row] = k4.w;
        }
        __syncthreads();
#pragma unroll
        for (int kk = 0; kk < 16; kk++) {
            float4 a4 = *reinterpret_cast<const float4*>(&Qs[kk][ty * 4]);
            float4 b4 = *reinterpret_cast<const float4*>(&Ks[kk][tx * 4]);
            float a[4] = {a4.x, a4.y, a4.z, a4.w};
            float bb[4] = {b4.x, b4.y, b4.z, b4.w};
#pragma unroll
            for (int i = 0; i < 4; i++)
#pragma unroll
                for (int j = 0; j < 4; j++)
                    acc[i][j] = fmaf(a[i], bb[j], acc[i][j]);
        }
        __syncthreads();
    }

#pragma unroll
    for (int i = 0; i < 4; i++) {
        int m = m0 + ty * 4 + i;
        int n = n0 + tx * 4;
        float4 o;
        o.x = acc[i][0] * scale + mask[b * Sk + n + 0];
        o.y = acc[i][1] * scale + mask[b * Sk + n + 1];
        o.z = acc[i][2] * scale + mask[b * Sk + n + 2];
        o.w = acc[i][3] * scale + mask[b * Sk + n + 3];
        *reinterpret_cast<float4*>(S + ((size_t)bh * Sq + m) * Sk + n) = o;
    }
}

// ---------------------------------------------------------------------------
// In-place row softmax; one warp per row.
// ---------------------------------------------------------------------------
__global__ __launch_bounds__(256) void softmax_rows(
    float* __restrict__ S, int rows, int n)
{
    int warp = (blockIdx.x * blockDim.x + threadIdx.x) >> 5;
    int lane = threadIdx.x & 31;
    if (warp >= rows) return;
    float* row = S + (size_t)warp * n;

    float mx = -INFINITY;
    for (int i = lane; i < n; i += 32) mx = fmaxf(mx, row[i]);
#pragma unroll
    for (int o = 16; o; o >>= 1) mx = fmaxf(mx, __shfl_xor_sync(0xffffffffu, mx, o));

    float sum = 0.f;
    for (int i = lane; i < n; i += 32) {
        float e = __expf(row[i] - mx);
        row[i] = e;
        sum += e;
    }
#pragma unroll
    for (int o = 16; o; o >>= 1) sum += __shfl_xor_sync(0xffffffffu, sum, o);
    float inv = 1.f / sum;
    for (int i = lane; i < n; i += 32) row[i] *= inv;
}

// ---------------------------------------------------------------------------
// O[b,m,h,d] = sum_n P[bh,m,n] * V[b,n,h,d]
// grid: (D/64=2, Sq/64, B*H), 256 threads, 64x64 tile, BK=16 (n)
// ---------------------------------------------------------------------------
__global__ __launch_bounds__(256) void attn_context(
    const float* __restrict__ P, const float* __restrict__ V,
    float* __restrict__ O, int Sq, int Sk)
{
    __shared__ float Ps[16][64 + 4];
    __shared__ float Vs[16][64 + 4];
    const int tid = threadIdx.x, tx = tid & 15, ty = tid >> 4;
    const int bh = blockIdx.z, b = bh >> 3, h = bh & 7;
    const int m0 = blockIdx.y * 64, d0 = blockIdx.x * 64;

    float acc[4][4];
#pragma unroll
    for (int i = 0; i < 4; i++)
#pragma unroll
        for (int j = 0; j < 4; j++) acc[i][j] = 0.f;

    for (int n0 = 0; n0 < Sk; n0 += 16) {
        {
            int v = tid;
            int row = v >> 2, nq = (v & 3) << 2;
            float4 p4 = *reinterpret_cast<const float4*>(
                P + ((size_t)bh * Sq + m0 + row) * Sk + n0 + nq);
            Ps[nq + 0][row] = p4.x; Ps[nq + 1][row] = p4.y;
            Ps[nq + 2][row] = p4.z; Ps[nq + 3][row] = p4.w;
            int vr = v >> 4, dq = (v & 15) << 2;
            float4 v4 = *reinterpret_cast<const float4*>(
                V + ((size_t)(b * Sk + n0 + vr) * HH + h) * DD + d0 + dq);
            *reinterpret_cast<float4*>(&Vs[vr][dq]) = v4;
        }
        __syncthreads();
#pragma unroll
        for (int kk = 0; kk < 16; kk++) {
            float4 a4 = *reinterpret_cast<const float4*>(&Ps[kk][ty * 4]);
            float4 b4 = *reinterpret_cast<const float4*>(&Vs[kk][tx * 4]);
            float a[4] = {a4.x, a4.y, a4.z, a4.w};
            float bb[4] = {b4.x, b4.y, b4.z, b4.w};
#pragma unroll
            for (int i = 0; i < 4; i++)
#pragma unroll
                for (int j = 0; j < 4; j++)
                    acc[i][j] = fmaf(a[i], bb[j], acc[i][j]);
        }
        __syncthreads();
    }

#pragma unroll
    for (int i = 0; i < 4; i++) {
        int m = m0 + ty * 4 + i, d = d0 + tx * 4;
        float4 o = make_float4(acc[i][0], acc[i][1], acc[i][2], acc[i][3]);
        *reinterpret_cast<float4*>(
            O + ((size_t)(b * Sq + m) * HH + h) * DD + d) = o;
    }
}

// ---------------------------------------------------------------------------
extern "C" void kernel_launch(void* const* d_in, const int* in_sizes, int n_in,
                              void* d_out, int out_size)
{
    const float* x1    = (const float*)d_in[0];
    const float* mask1 = (const float*)d_in[1];
    const float* x2    = (const float*)d_in[2];
    const float* mask2 = (const float*)d_in[3];
    const float* Wq1 = (const float*)d_in[4];  const float* bq1 = (const float*)d_in[5];
    const float* Wk1 = (const float*)d_in[6];  const float* bk1 = (const float*)d_in[7];
    const float* Wv1 = (const float*)d_in[8];  const float* bv1 = (const float*)d_in[9];
    const float* Wq2 = (const float*)d_in[10]; const float* bq2 = (const float*)d_in[11];
    const float* Wk2 = (const float*)d_in[12]; const float* bk2 = (const float*)d_in[13];
    const float* Wv2 = (const float*)d_in[14]; const float* bv2 = (const float*)d_in[15];
    float* out = (float*)d_out;

    float *q1, *k1, *v1, *q2, *k2, *v2, *p1, *p2;
    cudaGetSymbolAddress((void**)&q1, g_q1);
    cudaGetSymbolAddress((void**)&k1, g_k1);
    cudaGetSymbolAddress((void**)&v1, g_v1);
    cudaGetSymbolAddress((void**)&q2, g_q2);
    cudaGetSymbolAddress((void**)&k2, g_k2);
    cudaGetSymbolAddress((void**)&v2, g_v2);
    cudaGetSymbolAddress((void**)&p1, g_p1);
    cudaGetSymbolAddress((void**)&p2, g_p2);

    const float scale = 1.0f / sqrtf((float)DD);
    dim3 blk(256);

    // --- QKV projections ---
    // stream 1: M=4096, K=1024, N=1024
    sgemm_bias<<<dim3(8, 32), blk>>>(x1, Wq1, bq1, q1, BB * SS1, HD, 1024);
    sgemm_bias<<<dim3(8, 32), blk>>>(x1, Wk1, bk1, k1, BB * SS1, HD, 1024);
    sgemm_bias<<<dim3(8, 32), blk>>>(x1, Wv1, bv1, v1, BB * SS1, HD, 1024);
    // stream 2: M=8192, K=768, N=1024
    sgemm_bias<<<dim3(8, 64), blk>>>(x2, Wq2, bq2, q2, BB * SS2, HD, 768);
    sgemm_bias<<<dim3(8, 64), blk>>>(x2, Wk2, bk2, k2, BB * SS2, HD, 768);
    sgemm_bias<<<dim3(8, 64), blk>>>(x2, Wv2, bv2, v2, BB * SS2, HD, 768);

    // --- attention 1: text queries (q2) over vision keys/values (k1,v1) ---
    attn_scores<<<dim3(SS1 / 64, SS2 / 64, BB * HH), blk>>>(q2, k1, mask1, p1, SS2, SS1, scale);
    softmax_rows<<<(BB * HH * SS2) / 8, blk>>>(p1, BB * HH * SS2, SS1);
    attn_context<<<dim3(2, SS2 / 64, BB * HH), blk>>>(p1, v1, out, SS2, SS1);

    // --- attention 2: vision queries (q1) over text keys/values (k2,v2) ---
    attn_scores<<<dim3(SS2 / 64, SS1 / 64, BB * HH), blk>>>(q1, k2, mask2, p2, SS1, SS2, scale);
    softmax_rows<<<(BB * HH * SS1) / 8, blk>>>(p2, BB * HH * SS1, SS2);
    attn_context<<<dim3(2, SS1 / 64, BB * HH), blk>>>(p2, v2, out + C1_ELEMS, SS1, SS2);
}

// round 3
// speedup vs baseline: 1.5227x; 1.5227x over previous
#include <cuda_runtime.h>
#include <cuda_bf16.h>
#include <cstdint>
#include <math.h>

// ===========================================================================
// BertBiAttention on GB300 (sm_103 ptxas target: NO tcgen05 -> use mma.sync)
//   B=16, S1=256, S2=512, V_HID=1024, T_HID=768, BI_HID=1024, H=8, D=128
// Round 3: QKV projections via HMMA (bf16 hi/lo split, fp32 accum, 3 passes)
//          attention fp32 SIMT (unchanged, next target).
// ===========================================================================

#define BB   16
#define SS1  256
#define SS2  512
#define HH   8
#define DD   128
#define HD   1024
#define C1_ELEMS ((size_t)BB * SS2 * HD)

// ---------------- scratch ----------------
__device__ float g_q1[BB * SS1 * HD];
__device__ float g_k1[BB * SS1 * HD];
__device__ float g_v1[BB * SS1 * HD];
__device__ float g_q2[BB * SS2 * HD];
__device__ float g_k2[BB * SS2 * HD];
__device__ float g_v2[BB * SS2 * HD];
__device__ float g_p1[(size_t)BB * HH * SS2 * SS1];
__device__ float g_p2[(size_t)BB * HH * SS1 * SS2];

__device__ __nv_bfloat16 g_x1h[4096 * 1024];
__device__ __nv_bfloat16 g_x1l[4096 * 1024];
__device__ __nv_bfloat16 g_x2h[8192 * 768];
__device__ __nv_bfloat16 g_x2l[8192 * 768];
__device__ __nv_bfloat16 g_w1h[3][1024 * 1024];  // transposed [N][K]
__device__ __nv_bfloat16 g_w1l[3][1024 * 1024];
__device__ __nv_bfloat16 g_w2h[3][1024 * 768];
__device__ __nv_bfloat16 g_w2l[3][1024 * 768];

// ---------------- helpers ----------------
__device__ __forceinline__ uint32_t smem_u32(const void* p) {
    uint32_t a;
    asm("{ .reg .u64 t; cvta.to.shared.u64 t, %1; cvt.u32.u64 %0, t; }"
        : "=r"(a) : "l"(p));
    return a;
}
__device__ __forceinline__ void cp16(uint32_t dst, const void* src) {
    asm volatile("cp.async.cg.shared.global [%0], [%1], 16;\n" :: "r"(dst), "l"(src));
}
__device__ __forceinline__ void ldsm_x4(uint32_t& r0, uint32_t& r1,
                                        uint32_t& r2, uint32_t& r3, uint32_t a) {
    asm volatile("ldmatrix.sync.aligned.m8n8.x4.shared.b16 {%0,%1,%2,%3}, [%4];"
                 : "=r"(r0), "=r"(r1), "=r"(r2), "=r"(r3) : "r"(a));
}
__device__ __forceinline__ void mma16816(float* c, uint32_t a0, uint32_t a1,
                                         uint32_t a2, uint32_t a3,
                                         uint32_t b0, uint32_t b1) {
    asm volatile(
        "mma.sync.aligned.m16n8k16.row.col.f32.bf16.bf16.f32 "
        "{%0,%1,%2,%3}, {%4,%5,%6,%7}, {%8,%9}, {%0,%1,%2,%3};"
        : "+f"(c[0]), "+f"(c[1]), "+f"(c[2]), "+f"(c[3])
        : "r"(a0), "r"(a1), "r"(a2), "r"(a3), "r"(b0), "r"(b1));
}

// ---------------- split/convert ----------------
__device__ __forceinline__ uint32_t packbf(__nv_bfloat16 a, __nv_bfloat16 b) {
    __nv_bfloat162 t = __halves2bfloat162(a, b);
    return *reinterpret_cast<uint32_t*>(&t);
}

__global__ void xsplit(const float4* __restrict__ x,
                       uint2* __restrict__ h, uint2* __restrict__ l, int n4) {
    int i = blockIdx.x * blockDim.x + threadIdx.x;
    if (i >= n4) return;
    float4 v = x[i];
    __nv_bfloat16 h0 = __float2bfloat16(v.x), h1 = __float2bfloat16(v.y);
    __nv_bfloat16 h2 = __float2bfloat16(v.z), h3 = __float2bfloat16(v.w);
    float r0 = v.x - __bfloat162float(h0), r1 = v.y - __bfloat162float(h1);
    float r2 = v.z - __bfloat162float(h2), r3 = v.w - __bfloat162float(h3);
    uint2 hp, lp;
    hp.x = packbf(h0, h1); hp.y = packbf(h2, h3);
    lp.x = packbf(__float2bfloat16(r0), __float2bfloat16(r1));
    lp.y = packbf(__float2bfloat16(r2), __float2bfloat16(r3));
    h[i] = hp; l[i] = lp;
}

__global__ void wsplit(const float* __restrict__ W,
                       __nv_bfloat16* __restrict__ Wh, __nv_bfloat16* __restrict__ Wl,
                       int K, int N) {
    __shared__ float t[32][33];
    int k0 = blockIdx.y * 32, n0 = blockIdx.x * 32;
    int tx = threadIdx.x, ty = threadIdx.y;
#pragma unroll
    for (int i = 0; i < 4; i++)
        t[ty + i * 8][tx] = W[(size_t)(k0 + ty + i * 8) * N + n0 + tx];
    __syncthreads();
#pragma unroll
    for (int i = 0; i < 4; i++) {
        float v = t[tx][ty + i * 8];
        __nv_bfloat16 h = __float2bfloat16(v);
        float lo = v - __bfloat162float(h);
        size_t o = (size_t)(n0 + ty + i * 8) * K + k0 + tx;
        Wh[o] = h;
        Wl[o] = __float2bfloat16(lo);
    }
}

// ---------------------------------------------------------------------------
// HMMA GEMM: out[z][M,1024] = A[M,K] @ Wt[z][1024,K]^T + bias[z]
// 3-pass split compensation. BM=BN=128, BK=32, 256 threads, 8 warps (2m x 4n),
// warp tile 64x32, double-buffered cp.async, padded smem rows (40 bf16 = 80B).
// ---------------------------------------------------------------------------
struct G3 {
    const __nv_bfloat16* Wh[3];
    const __nv_bfloat16* Wl[3];
    const float* bias[3];
    float* out[3];
};

#define PADK 40   // smem row stride in bf16 elems (80 bytes)

__global__ __launch_bounds__(256) void hmma_gemm3(
    const __nv_bfloat16* __restrict__ Ah, const __nv_bfloat16* __restrict__ Al,
    G3 g, int M, int K) {
    const int N = 1024;
    __shared__ __align__(128) __nv_bfloat16 As[2][128 * PADK];
    __shared__ __align__(128) __nv_bfloat16 Bs[2][128 * PADK];

    const int tid = threadIdx.x;
    const int wid = tid >> 5, lane = tid & 31;
    const int wm = wid >> 2, wn = wid & 3;     // 2 x 4 warp grid
    const int z = blockIdx.z;
    const int bm = blockIdx.y * 128, bn = blockIdx.x * 128;
    const int nk = K / 32;
    const int C = 3 * nk;

    const __nv_bfloat16* Wh = g.Wh[z];
    const __nv_bfloat16* Wl = g.Wl[z];

    float acc[4][4][4];
#pragma unroll
    for (int i = 0; i < 4; i++)
#pragma unroll
        for (int j = 0; j < 4; j++)
#pragma unroll
            for (int r = 0; r < 4; r++) acc[i][j][r] = 0.f;

    const uint32_t asb = smem_u32(&As[0][0]);
    const uint32_t bsb = smem_u32(&Bs[0][0]);
    const uint32_t stageB = 128 * PADK * 2;    // bytes per stage

    // cp.async segment assignment: 512 A segs + 512 B segs, 4 per thread
    const int r0 = tid >> 2, s0 = (tid & 3);   // A seg: tid, tid+256
    // per-lane ldmatrix bases (byte offsets within a stage)
    const uint32_t a_lm = (uint32_t)((wm * 64 + (lane & 15)) * (PADK * 2) + (lane >> 4) * 16);
    const uint32_t b_lm = (uint32_t)((wn * 32 + (lane & 15)) * (PADK * 2) + (lane >> 4) * 16);

    auto load_stage = [&](int c, int buf) {
        const int p = c / nk, kc = c - p * nk;
        const __nv_bfloat16* Ap = (p < 2) ? Ah : Al;
        const __nv_bfloat16* Bp = (p == 1) ? Wl : Wh;
        const char* ab = (const char*)(Ap + (size_t)bm * K + kc * 32);
        const char* bb = (const char*)(Bp + (size_t)bn * K + kc * 32);
        const size_t rs = (size_t)K * 2;
        const uint32_t sa = asb + buf * stageB;
        const uint32_t sb2 = bsb + buf * stageB;
#pragma unroll
        for (int u = 0; u < 2; u++) {
            int row = r0 + u * 64;
            uint32_t off = (uint32_t)(row * (PADK * 2) + s0 * 16);
            cp16(sa + off, ab + (size_t)row * rs + s0 * 16);
            cp16(sb2 + off, bb + (size_t)row * rs + s0 * 16);
        }
        asm volatile("cp.async.commit_group;\n");
    };

    load_stage(0, 0);

    for (int c = 0; c < C; ++c) {
        if (c + 1 < C) {
            load_stage(c + 1, (c + 1) & 1);
            asm volatile("cp.async.wait_group 1;\n");
        } else {
            asm volatile("cp.async.wait_group 0;\n");
        }
        __syncthreads();

        const int buf = c & 1;
        const uint32_t sa = asb + buf * stageB + a_lm;
        const uint32_t sb2 = bsb + buf * stageB + b_lm;
#pragma unroll
        for (int kk = 0; kk < 2; kk++) {       // two k16 steps in BK=32
            uint32_t a[4][4], bbf[2][4];
#pragma unroll
            for (int i = 0; i < 4; i++)
                ldsm_x4(a[i][0], a[i][1], a[i][2], a[i][3],
                        sa + i * 16 * (PADK * 2) + kk * 32);
#pragma unroll
            for (int j2 = 0; j2 < 2; j2++)
                ldsm_x4(bbf[j2][0], bbf[j2][1], bbf[j2][2], bbf[j2][3],
                        sb2 + j2 * 16 * (PADK * 2) + kk * 32);
#pragma unroll
            for (int i = 0; i < 4; i++)
#pragma unroll
                for (int j = 0; j < 4; j++) {
                    int j2 = j >> 1, jo = j & 1;
                    mma16816(acc[i][j], a[i][0], a[i][1], a[i][2], a[i][3],
                             bbf[j2][jo], bbf[j2][jo + 2]);
                }
        }
        __syncthreads();
    }

    // epilogue
    float* outp = g.out[z];
    const float* bias = g.bias[z];
#pragma unroll
    for (int i = 0; i < 4; i++) {
#pragma unroll
        for (int j = 0; j < 4; j++) {
            int m = bm + wm * 64 + i * 16 + (lane >> 2);
            int n = bn + wn * 32 + j * 8 + (lane & 3) * 2;
            float b0 = __ldg(bias + n), b1 = __ldg(bias + n + 1);
            float2 v0 = make_float2(acc[i][j][0] + b0, acc[i][j][1] + b1);
            float2 v1 = make_float2(acc[i][j][2] + b0, acc[i][j][3] + b1);
            *reinterpret_cast<float2*>(outp + (size_t)m * N + n) = v0;
            *reinterpret_cast<float2*>(outp + (size_t)(m + 8) * N + n) = v1;
        }
    }
}

// ---------------------------------------------------------------------------
// Attention (fp32 SIMT, unchanged)
// ---------------------------------------------------------------------------
__global__ __launch_bounds__(256) void attn_scores(
    const float* __restrict__ Q, const float* __restrict__ Km,
    const float* __restrict__ mask, float* __restrict__ S,
    int Sq, int Sk, float scale) {
    __shared__ float Qs[16][64 + 4];
    __shared__ float Ks[16][64 + 4];
    const int tid = threadIdx.x, tx = tid & 15, ty = tid >> 4;
    const int bh = blockIdx.z, b = bh >> 3, h = bh & 7;
    const int m0 = blockIdx.y * 64, n0 = blockIdx.x * 64;

    float acc[4][4];
#pragma unroll
    for (int i = 0; i < 4; i++)
#pragma unroll
        for (int j = 0; j < 4; j++) acc[i][j] = 0.f;

    for (int d0 = 0; d0 < DD; d0 += 16) {
        {
            int v = tid;
            int row = v >> 2, dq = (v & 3) << 2;
            float4 q4 = *reinterpret_cast<const float4*>(
                Q + ((size_t)(b * Sq + m0 + row) * HH + h) * DD + d0 + dq);
            Qs[dq + 0][row] = q4.x; Qs[dq + 1][row] = q4.y;
            Qs[dq + 2][row] = q4.z; Qs[dq + 3][row] = q4.w;
            float4 k4 = *reinterpret_cast<const float4*>(
                Km + ((size_t)(b * Sk + n0 + row) * HH + h) * DD + d0 + dq);
            Ks[dq + 0][row] = k4.x; Ks[dq + 1][row] = k4.y;
            Ks[dq + 2][row] = k4.z; Ks[dq + 3][row] = k4.w;
        }
        __syncthreads();
#pragma unroll
        for (int kk = 0; kk < 16; kk++) {
            float4 a4 = *reinterpret_cast<const float4*>(&Qs[kk][ty * 4]);
            float4 b4 = *reinterpret_cast<const float4*>(&Ks[kk][tx * 4]);
            float a[4] = {a4.x, a4.y, a4.z, a4.w};
            float bb[4] = {b4.x, b4.y, b4.z, b4.w};
#pragma unroll
            for (int i = 0; i < 4; i++)
#pragma unroll
                for (int j = 0; j < 4; j++)
                    acc[i][j] = fmaf(a[i], bb[j], acc[i][j]);
        }
        __syncthreads();
    }

#pragma unroll
    for (int i = 0; i < 4; i++) {
        int m = m0 + ty * 4 + i;
        int n = n0 + tx * 4;
        float4 o;
        o.x = acc[i][0] * scale + mask[b * Sk + n + 0];
        o.y = acc[i][1] * scale + mask[b * Sk + n + 1];
        o.z = acc[i][2] * scale + mask[b * Sk + n + 2];
        o.w = acc[i][3] * scale + mask[b * Sk + n + 3];
        *reinterpret_cast<float4*>(S + ((size_t)bh * Sq + m) * Sk + n) = o;
    }
}

__global__ __launch_bounds__(256) void softmax_rows(
    float* __restrict__ S, int rows, int n) {
    int warp = (blockIdx.x * blockDim.x + threadIdx.x) >> 5;
    int lane = threadIdx.x & 31;
    if (warp >= rows) return;
    float* row = S + (size_t)warp * n;

    float mx = -INFINITY;
    for (int i = lane; i < n; i += 32) mx = fmaxf(mx, row[i]);
#pragma unroll
    for (int o = 16; o; o >>= 1) mx = fmaxf(mx, __shfl_xor_sync(0xffffffffu, mx, o));

    float sum = 0.f;
    for (int i = lane; i < n; i += 32) {
        float e = __expf(row[i] - mx);
        row[i] = e;
        sum += e;
    }
#pragma unroll
    for (int o = 16; o; o >>= 1) sum += __shfl_xor_sync(0xffffffffu, sum, o);
    float inv = 1.f / sum;
    for (int i = lane; i < n; i += 32) row[i] *= inv;
}

__global__ __launch_bounds__(256) void attn_context(
    const float* __restrict__ P, const float* __restrict__ V,
    float* __restrict__ O, int Sq, int Sk) {
    __shared__ float Ps[16][64 + 4];
    __shared__ float Vs[16][64 + 4];
    const int tid = threadIdx.x, tx = tid & 15, ty = tid >> 4;
    const int bh = blockIdx.z, b = bh >> 3, h = bh & 7;
    const int m0 = blockIdx.y * 64, d0 = blockIdx.x * 64;

    float acc[4][4];
#pragma unroll
    for (int i = 0; i < 4; i++)
#pragma unroll
        for (int j = 0; j < 4; j++) acc[i][j] = 0.f;

    for (int n0 = 0; n0 < Sk; n0 += 16) {
        {
            int v = tid;
            int row = v >> 2, nq = (v & 3) << 2;
            float4 p4 = *reinterpret_cast<const float4*>(
                P + ((size_t)bh * Sq + m0 + row) * Sk + n0 + nq);
            Ps[nq + 0][row] = p4.x; Ps[nq + 1][row] = p4.y;
            Ps[nq + 2][row] = p4.z; Ps[nq + 3][row] = p4.w;
            int vr = v >> 4, dq = (v & 15) << 2;
            float4 v4 = *reinterpret_cast<const float4*>(
                V + ((size_t)(b * Sk + n0 + vr) * HH + h) * DD + d0 + dq);
            *reinterpret_cast<float4*>(&Vs[vr][dq]) = v4;
        }
        __syncthreads();
#pragma unroll
        for (int kk = 0; kk < 16; kk++) {
            float4 a4 = *reinterpret_cast<const float4*>(&Ps[kk][ty * 4]);
            float4 b4 = *reinterpret_cast<const float4*>(&Vs[kk][tx * 4]);
            float a[4] = {a4.x, a4.y, a4.z, a4.w};
            float bb[4] = {b4.x, b4.y, b4.z, b4.w};
#pragma unroll
            for (int i = 0; i < 4; i++)
#pragma unroll
                for (int j = 0; j < 4; j++)
                    acc[i][j] = fmaf(a[i], bb[j], acc[i][j]);
        }
        __syncthreads();
    }

#pragma unroll
    for (int i = 0; i < 4; i++) {
        int m = m0 + ty * 4 + i, d = d0 + tx * 4;
        float4 o = make_float4(acc[i][0], acc[i][1], acc[i][2], acc[i][3]);
        *reinterpret_cast<float4*>(
            O + ((size_t)(b * Sq + m) * HH + h) * DD + d) = o;
    }
}

// ---------------------------------------------------------------------------
extern "C" void kernel_launch(void* const* d_in, const int* in_sizes, int n_in,
                              void* d_out, int out_size) {
    const float* x1    = (const float*)d_in[0];
    const float* mask1 = (const float*)d_in[1];
    const float* x2    = (const float*)d_in[2];
    const float* mask2 = (const float*)d_in[3];
    const float* W1[3] = {(const float*)d_in[4], (const float*)d_in[6], (const float*)d_in[8]};
    const float* b1[3] = {(const float*)d_in[5], (const float*)d_in[7], (const float*)d_in[9]};
    const float* W2[3] = {(const float*)d_in[10], (const float*)d_in[12], (const float*)d_in[14]};
    const float* b2[3] = {(const float*)d_in[11], (const float*)d_in[13], (const float*)d_in[15]};
    float* out = (float*)d_out;

    float *q1, *k1, *v1, *q2, *k2, *v2, *p1, *p2;
    cudaGetSymbolAddress((void**)&q1, g_q1);
    cudaGetSymbolAddress((void**)&k1, g_k1);
    cudaGetSymbolAddress((void**)&v1, g_v1);
    cudaGetSymbolAddress((void**)&q2, g_q2);
    cudaGetSymbolAddress((void**)&k2, g_k2);
    cudaGetSymbolAddress((void**)&v2, g_v2);
    cudaGetSymbolAddress((void**)&p1, g_p1);
    cudaGetSymbolAddress((void**)&p2, g_p2);

    __nv_bfloat16 *x1h, *x1l, *x2h, *x2l, *w1h, *w1l, *w2h, *w2l;
    cudaGetSymbolAddress((void**)&x1h, g_x1h);
    cudaGetSymbolAddress((void**)&x1l, g_x1l);
    cudaGetSymbolAddress((void**)&x2h, g_x2h);
    cudaGetSymbolAddress((void**)&x2l, g_x2l);
    cudaGetSymbolAddress((void**)&w1h, g_w1h);
    cudaGetSymbolAddress((void**)&w1l, g_w1l);
    cudaGetSymbolAddress((void**)&w2h, g_w2h);
    cudaGetSymbolAddress((void**)&w2l, g_w2l);

    const float scale = 1.0f / sqrtf((float)DD);
    dim3 blk(256);

    // --- split/convert ---
    {
        int n4 = 4096 * 1024 / 4;
        xsplit<<<n4 / 256, 256>>>((const float4*)x1, (uint2*)x1h, (uint2*)x1l, n4);
    }
    {
        int n4 = 8192 * 768 / 4;
        xsplit<<<n4 / 256, 256>>>((const float4*)x2, (uint2*)x2h, (uint2*)x2l, n4);
    }
    for (int i = 0; i < 3; i++) {
        wsplit<<<dim3(32, 32), dim3(32, 8)>>>(W1[i], w1h + (size_t)i * 1024 * 1024,
                                              w1l + (size_t)i * 1024 * 1024, 1024, 1024);
        wsplit<<<dim3(32, 24), dim3(32, 8)>>>(W2[i], w2h + (size_t)i * 1024 * 768,
                                              w2l + (size_t)i * 1024 * 768, 768, 1024);
    }

    // --- QKV projections on HMMA ---
    {
        G3 g;
        for (int i = 0; i < 3; i++) {
            g.Wh[i] = w1h + (size_t)i * 1024 * 1024;
            g.Wl[i] = w1l + (size_t)i * 1024 * 1024;
            g.bias[i] = b1[i];
        }
        g.out[0] = q1; g.out[1] = k1; g.out[2] = v1;
        hmma_gemm3<<<dim3(8, 32, 3), blk>>>(x1h, x1l, g, BB * SS1, 1024);
    }
    {
        G3 g;
        for (int i = 0; i < 3; i++) {
            g.Wh[i] = w2h + (size_t)i * 1024 * 768;
            g.Wl[i] = w2l + (size_t)i * 1024 * 768;
            g.bias[i] = b2[i];
        }
        g.out[0] = q2; g.out[1] = k2; g.out[2] = v2;
        hmma_gemm3<<<dim3(8, 64, 3), blk>>>(x2h, x2l, g, BB * SS2, 768);
    }

    // --- attention 1: text queries (q2) over vision keys/values (k1,v1) ---
    attn_scores<<<dim3(SS1 / 64, SS2 / 64, BB * HH), blk>>>(q2, k1, mask1, p1, SS2, SS1, scale);
    softmax_rows<<<(BB * HH * SS2) / 8, blk>>>(p1, BB * HH * SS2, SS1);
    attn_context<<<dim3(2, SS2 / 64, BB * HH), blk>>>(p1, v1, out, SS2, SS1);

    // --- attention 2: vision queries (q1) over text keys/values (k2,v2) ---
    attn_scores<<<dim3(SS2 / 64, SS1 / 64, BB * HH), blk>>>(q1, k2, mask2, p2, SS1, SS2, scale);
    softmax_rows<<<(BB * HH * SS1) / 8, blk>>>(p2, BB * HH * SS1, SS2);
    attn_context<<<dim3(2, SS1 / 64, BB * HH), blk>>>(p2, v2, out + C1_ELEMS, SS1, SS2);
}